// round 15
// baseline (speedup 1.0000x reference)
#include <cuda_runtime.h>
#include <cuda_fp16.h>
#include <math.h>
#include <stdint.h>

#define T_SEQ 2048
#define BATCH 2
#define CDIM  2048
#define HEADS 16
#define HD    128
#define DSTD  120
#define RLOW  8
#define FDIM  6144

// ---------------- scratch (device globals; no allocations) ----------------
__device__ __align__(16) __half g_xh[(size_t)BATCH * T_SEQ * CDIM];
__device__ __align__(16) __half g_Wah[(size_t)FDIM * CDIM];
__device__ __align__(16) __half g_Wph[(size_t)CDIM * CDIM];
__device__ __align__(16) __half g_atth[(size_t)BATCH * T_SEQ * CDIM];
__device__ __align__(16) __half g_Qh[(size_t)BATCH * HEADS * T_SEQ * HD];
__device__ __align__(16) __half g_Kh[(size_t)BATCH * HEADS * T_SEQ * HD];
__device__ __align__(16) __half g_Vh[(size_t)BATCH * HEADS * T_SEQ * HD];

// ---------------- PTX helpers ----------------------------------------------
__device__ __forceinline__ uint32_t smem_u32(const void* p) {
    uint32_t a;
    asm("{ .reg .u64 t; cvta.to.shared.u64 t, %1; cvt.u32.u64 %0, t; }"
        : "=r"(a) : "l"(p));
    return a;
}
__device__ __forceinline__ void cp16(uint32_t saddr, const void* gaddr) {
    asm volatile("cp.async.cg.shared.global [%0], [%1], 16;"
                 :: "r"(saddr), "l"(gaddr) : "memory");
}
__device__ __forceinline__ void ldsm_x4(uint32_t* r, uint32_t addr) {
    asm volatile("ldmatrix.sync.aligned.m8n8.x4.shared.b16 {%0,%1,%2,%3}, [%4];"
                 : "=r"(r[0]), "=r"(r[1]), "=r"(r[2]), "=r"(r[3]) : "r"(addr));
}
__device__ __forceinline__ void ldsm_x4_t(uint32_t* r, uint32_t addr) {
    asm volatile("ldmatrix.sync.aligned.m8n8.x4.trans.shared.b16 {%0,%1,%2,%3}, [%4];"
                 : "=r"(r[0]), "=r"(r[1]), "=r"(r[2]), "=r"(r[3]) : "r"(addr));
}
__device__ __forceinline__ void mma16816(float* c, const uint32_t* a,
                                         uint32_t b0, uint32_t b1) {
    asm volatile(
        "mma.sync.aligned.m16n8k16.row.col.f32.f16.f16.f32 "
        "{%0,%1,%2,%3},{%4,%5,%6,%7},{%8,%9},{%0,%1,%2,%3};"
        : "+f"(c[0]), "+f"(c[1]), "+f"(c[2]), "+f"(c[3])
        : "r"(a[0]), "r"(a[1]), "r"(a[2]), "r"(a[3]), "r"(b0), "r"(b1));
}

// ---------------- HMMA GEMM: C[M,N]=A[M,K]*B[N,K]^T, compile-time KT --------
// block 128x128, warp 64x32 (8 warps), BK=64, 3-stage cp.async, KT=K/64=32.
#define GSMEM (3 * 32768)
#define KT_C  32   // both GEMMs have K = 2048

template <int EPI>
__global__ void __launch_bounds__(256, 2)
hgemm_mma(const __half* __restrict__ A, const __half* __restrict__ B,
          float* __restrict__ C,
          const float* __restrict__ w_std, const float* __restrict__ w_rec,
          __half* __restrict__ Qd, __half* __restrict__ Kd,
          __half* __restrict__ Vd, int M, int N) {
    constexpr int K = KT_C * 64;
    extern __shared__ __align__(1024) char smem_raw[];
    const uint32_t smem = smem_u32(smem_raw);
    const int tid = threadIdx.x;
    const int wid = tid >> 5;
    const int lid = tid & 31;
    const int m0 = blockIdx.y << 7;
    const int n0 = blockIdx.x << 7;
    const int wm0 = (wid & 1) << 6;
    const int wn0 = (wid >> 1) << 5;

    const int r = tid >> 1;
    const int hs = tid & 1;
    const __half* Ag = A + (size_t)(m0 + r) * K + hs * 32;
    const __half* Bg = B + (size_t)(n0 + r) * K + hs * 32;
    const uint32_t swb = r * 128 + hs * 64;

    auto load_stage = [&](int kt, int s) {
        uint32_t ab = smem + s * 32768;
        uint32_t bb = ab + 16384;
        const __half* ag = Ag + kt * 64;
        const __half* bg = Bg + kt * 64;
#pragma unroll
        for (int j = 0; j < 4; j++) {
            uint32_t off = swb + j * 16;
            uint32_t sw = off ^ ((off >> 3) & 0x70);
            cp16(ab + sw, ag + j * 8);
            cp16(bb + sw, bg + j * 8);
        }
        asm volatile("cp.async.commit_group;" ::: "memory");
    };

    float acc[4][4][4];
#pragma unroll
    for (int mt = 0; mt < 4; mt++)
#pragma unroll
        for (int nt = 0; nt < 4; nt++)
#pragma unroll
            for (int e = 0; e < 4; e++) acc[mt][nt][e] = 0.f;

    load_stage(0, 0);
    load_stage(1, 1);

    const int grp = lid >> 3;
    const int lr = lid & 7;
    const int arow = wm0 + ((grp & 1) << 3) + lr;
    const int acol = (grp >> 1) << 3;
    const int brow = wn0 + ((grp & 1) << 3) + lr;

    auto compute_tile = [&](int s) {
        const uint32_t ab = smem + s * 32768;
        const uint32_t bb = ab + 16384;
#pragma unroll
        for (int ks = 0; ks < 4; ks++) {
            uint32_t a_regs[4][4];
#pragma unroll
            for (int mt = 0; mt < 4; mt++) {
                uint32_t off = (uint32_t)(arow + mt * 16) * 128 + (acol + ks * 16) * 2;
                ldsm_x4(a_regs[mt], ab + (off ^ ((off >> 3) & 0x70)));
            }
            uint32_t b_regs[2][4];
#pragma unroll
            for (int np = 0; np < 2; np++) {
                uint32_t off = (uint32_t)(brow + np * 16) * 128 + (acol + ks * 16) * 2;
                ldsm_x4(b_regs[np], bb + (off ^ ((off >> 3) & 0x70)));
            }
#pragma unroll
            for (int mt = 0; mt < 4; mt++)
#pragma unroll
                for (int nt = 0; nt < 4; nt++) {
                    uint32_t b0 = b_regs[nt >> 1][nt & 1];
                    uint32_t b1 = b_regs[nt >> 1][(nt & 1) + 2];
                    mma16816(acc[mt][nt], a_regs[mt], b0, b1);
                }
        }
    };

    // body: KT-2 = 30 iterations, unroll 15 (stage ids become immediates)
#pragma unroll 15
    for (int kt = 0; kt < KT_C - 2; kt++) {
        asm volatile("cp.async.wait_group 1;" ::: "memory");
        __syncthreads();
        load_stage(kt + 2, (kt + 2) % 3);
        compute_tile(kt % 3);
    }
    asm volatile("cp.async.wait_group 1;" ::: "memory");
    __syncthreads();
    compute_tile((KT_C - 2) % 3);
    asm volatile("cp.async.wait_group 0;" ::: "memory");
    __syncthreads();
    compute_tile((KT_C - 1) % 3);

    const int row0 = m0 + wm0 + (lid >> 2);
    const int col0 = n0 + wn0 + (lid & 3) * 2;

    if (EPI == 0) {
#pragma unroll
        for (int mt = 0; mt < 4; mt++)
#pragma unroll
            for (int nt = 0; nt < 4; nt++) {
                float* p0 = C + (size_t)(row0 + mt * 16) * N + col0 + nt * 8;
                float* p1 = C + (size_t)(row0 + mt * 16 + 8) * N + col0 + nt * 8;
                *(float2*)p0 = make_float2(acc[mt][nt][0], acc[mt][nt][1]);
                *(float2*)p1 = make_float2(acc[mt][nt][2], acc[mt][nt][3]);
            }
    } else {
        const float ascale = 0.08838834764831845f;  // 1/sqrt(128)
        const int b = m0 >> 11;
#pragma unroll
        for (int nt = 0; nt < 4; nt++) {
            int f = col0 + nt * 8;
            __half* dst;
            int h, d;
            float scl;
            if (f < 1920) {
                h = f / 120; d = f - h * 120;
                scl = sqrtf(fmaxf(w_std[h], 1e-8f)) * ascale;
                dst = Qd;
            } else if (f < 3840) {
                int g = f - 1920; h = g / 120; d = g - h * 120;
                scl = sqrtf(fmaxf(w_std[h], 1e-8f));
                dst = Kd;
            } else if (f < 5888) {
                int g = f - 3840; h = g >> 7; d = g & 127;
                scl = 1.f;
                dst = Vd;
            } else if (f < 6016) {
                int g = f - 5888; h = g >> 3; d = 120 + (g & 7);
                float wrv = w_rec[h];
                if (wrv > 0.1f) { scl = sqrtf(fmaxf(wrv, 1e-8f)); dst = Kd; }
                else { scl = sqrtf(fmaxf(w_std[h], 1e-8f)) * ascale; dst = Qd; }
            } else {
                int g = f - 6016; h = g >> 3; d = 120 + (g & 7);
                float wrv = w_rec[h];
                if (wrv > 0.1f) { scl = sqrtf(fmaxf(wrv, 1e-8f)) * ascale; dst = Qd; }
                else { scl = sqrtf(fmaxf(w_std[h], 1e-8f)); dst = Kd; }
            }
            __half* base = dst + (((size_t)(b * HEADS + h)) << 18) + d;
#pragma unroll
            for (int mt = 0; mt < 4; mt++) {
                int t0 = (row0 + mt * 16) & (T_SEQ - 1);
                *(__half2*)(base + ((size_t)t0 << 7)) =
                    __floats2half2_rn(acc[mt][nt][0] * scl, acc[mt][nt][1] * scl);
                *(__half2*)(base + ((size_t)(t0 + 8) << 7)) =
                    __floats2half2_rn(acc[mt][nt][2] * scl, acc[mt][nt][3] * scl);
            }
        }
    }
}

// ---------------- fused fp32 -> fp16 conversion (3 arrays, 1 launch) -------
__global__ void f2h3(const float* __restrict__ a, __half* __restrict__ oa_, int na4,
                     const float* __restrict__ b, __half* __restrict__ ob_, int nb4,
                     const float* __restrict__ c, __half* __restrict__ oc_, int nc4) {
    int i = blockIdx.x * blockDim.x + threadIdx.x;
    const float* src;
    __half* dst;
    if (i < na4) { src = a; dst = oa_; }
    else if (i < na4 + nb4) { i -= na4; src = b; dst = ob_; }
    else { i -= na4 + nb4; if (i >= nc4) return; src = c; dst = oc_; }
    float4 v = ((const float4*)src)[i];
    ((__half2*)dst)[2 * i] = __floats2half2_rn(v.x, v.y);
    ((__half2*)dst)[2 * i + 1] = __floats2half2_rn(v.z, v.w);
}

// ---------------- HMMA causal flash attention ------------------------------
// 64-query tile, Q in regs, 2-stage KV cp.async, tensor-core row sums,
// heavy-first 1D grid, overlapped Q/KV startup, coalesced smem-staged O.
#define ASMEM 65536
#define OROWH 136
#define ONES_H2 0x3C003C00u  // half2(1.0, 1.0)
__device__ __forceinline__ uint32_t swoff(int row, int c16) {
    return (uint32_t)row * 256 + (uint32_t)((c16 ^ (row & 7)) * 16);
}

__global__ void __launch_bounds__(128, 3)
attn_mma(const __half* __restrict__ Qh, const __half* __restrict__ Kh,
         const __half* __restrict__ Vh, __half* __restrict__ out) {
    extern __shared__ __align__(1024) char smem_raw[];
    const uint32_t sb = smem_u32(smem_raw);
    const int tid = threadIdx.x;
    const int wid = tid >> 5;
    const int lid = tid & 31;
    const int grp = lid >> 3;
    const int lr = lid & 7;
    const int bh = blockIdx.x & 31;
    const int qi = (T_SEQ / 64 - 1) - (blockIdx.x >> 5);  // globally heavy-first
    const int b = bh >> 4;
    const int h = bh & 15;
    const int q0 = qi << 6;
    const int nkt = qi + 1;

    // Q staged in stage-1 K region [32K,48K); KV(1) deferred until Q consumed.
    const __half* Qg = Qh + ((size_t)bh * T_SEQ + q0) * HD;
    {
        uint32_t qb = sb + 32768;
#pragma unroll
        for (int i = 0; i < 8; i++) {
            int idx = tid + i * 128;
            int row = idx >> 4;
            int c = idx & 15;
            cp16(qb + swoff(row, c), Qg + (size_t)row * HD + c * 8);
        }
        asm volatile("cp.async.commit_group;" ::: "memory");
    }

    auto load_kv = [&](int kt, int s) {
        const __half* Kg = Kh + ((size_t)bh * T_SEQ + kt * 64) * HD;
        const __half* Vg = Vh + ((size_t)bh * T_SEQ + kt * 64) * HD;
        uint32_t kb = sb + (uint32_t)s * 32768;
        uint32_t vb = kb + 16384;
#pragma unroll
        for (int i = 0; i < 8; i++) {
            int idx = tid + i * 128;
            int row = idx >> 4;
            int c = idx & 15;
            uint32_t o = swoff(row, c);
            cp16(kb + o, Kg + (size_t)row * HD + c * 8);
            cp16(vb + o, Vg + (size_t)row * HD + c * 8);
        }
        asm volatile("cp.async.commit_group;" ::: "memory");
    };

    load_kv(0, 0);
    asm volatile("cp.async.wait_group 1;" ::: "memory");
    __syncthreads();

    uint32_t qf[8][4];
    {
        uint32_t qb = sb + 32768;
        int arow = (wid << 4) + ((grp & 1) << 3) + lr;
        int ach = (grp >> 1);
#pragma unroll
        for (int ks = 0; ks < 8; ks++)
            ldsm_x4(qf[ks], qb + swoff(arow, ks * 2 + ach));
    }
    __syncthreads();
    if (nkt > 1) load_kv(1, 1);

    float oa[16][4];
#pragma unroll
    for (int ot = 0; ot < 16; ot++)
#pragma unroll
        for (int e = 0; e < 4; e++) oa[ot][e] = 0.f;
    float lacc[4] = {0.f, 0.f, 0.f, 0.f};
    float m0 = -1e30f, m1 = -1e30f;

    for (int kt = 0; kt < nkt; kt++) {
        const int s = kt & 1;
        if (kt + 1 < nkt)
            asm volatile("cp.async.wait_group 1;" ::: "memory");
        else
            asm volatile("cp.async.wait_group 0;" ::: "memory");
        __syncthreads();

        const uint32_t kb = sb + (uint32_t)s * 32768;
        const uint32_t vb = kb + 16384;

        float sa[8][4];
#pragma unroll
        for (int nt = 0; nt < 8; nt++)
#pragma unroll
            for (int e = 0; e < 4; e++) sa[nt][e] = 0.f;

        const int brb = ((grp & 1) << 3) + lr;
        const int bch = (grp >> 1);
#pragma unroll
        for (int ks = 0; ks < 8; ks++) {
            uint32_t br[4][4];
#pragma unroll
            for (int np = 0; np < 4; np++)
                ldsm_x4(br[np], kb + swoff(np * 16 + brb, ks * 2 + bch));
#pragma unroll
            for (int nt = 0; nt < 8; nt++)
                mma16816(sa[nt], qf[ks], br[nt >> 1][nt & 1], br[nt >> 1][(nt & 1) + 2]);
        }

        if (kt == qi) {
            int qr = (wid << 4) + (lid >> 2);
#pragma unroll
            for (int nt = 0; nt < 8; nt++) {
                int cb = nt * 8 + ((lid & 3) << 1);
#pragma unroll
                for (int e = 0; e < 4; e++) {
                    int col = cb + (e & 1);
                    int row = qr + ((e >> 1) << 3);
                    if (col > row) sa[nt][e] = -1e30f;
                }
            }
        }

        float mx0 = -1e30f, mx1 = -1e30f;
#pragma unroll
        for (int nt = 0; nt < 8; nt++) {
            mx0 = fmaxf(mx0, fmaxf(sa[nt][0], sa[nt][1]));
            mx1 = fmaxf(mx1, fmaxf(sa[nt][2], sa[nt][3]));
        }
        mx0 = fmaxf(mx0, __shfl_xor_sync(0xffffffffu, mx0, 1));
        mx0 = fmaxf(mx0, __shfl_xor_sync(0xffffffffu, mx0, 2));
        mx1 = fmaxf(mx1, __shfl_xor_sync(0xffffffffu, mx1, 1));
        mx1 = fmaxf(mx1, __shfl_xor_sync(0xffffffffu, mx1, 2));

        float mn0 = fmaxf(m0, mx0), mn1 = fmaxf(m1, mx1);
        float al0 = __expf(m0 - mn0), al1 = __expf(m1 - mn1);
        m0 = mn0; m1 = mn1;

#pragma unroll
        for (int nt = 0; nt < 8; nt++) {
            sa[nt][0] = __expf(sa[nt][0] - mn0);
            sa[nt][1] = __expf(sa[nt][1] - mn0);
            sa[nt][2] = __expf(sa[nt][2] - mn1);
            sa[nt][3] = __expf(sa[nt][3] - mn1);
        }

#pragma unroll
        for (int ot = 0; ot < 16; ot++) {
            oa[ot][0] *= al0; oa[ot][1] *= al0;
            oa[ot][2] *= al1; oa[ot][3] *= al1;
        }
        lacc[0] *= al0;
        lacc[2] *= al1;

#pragma unroll
        for (int kp = 0; kp < 4; kp++) {
            uint32_t av[4];
            __half2 t0h = __floats2half2_rn(sa[2 * kp][0], sa[2 * kp][1]);
            __half2 t1h = __floats2half2_rn(sa[2 * kp][2], sa[2 * kp][3]);
            __half2 t2h = __floats2half2_rn(sa[2 * kp + 1][0], sa[2 * kp + 1][1]);
            __half2 t3h = __floats2half2_rn(sa[2 * kp + 1][2], sa[2 * kp + 1][3]);
            av[0] = *(uint32_t*)&t0h;
            av[1] = *(uint32_t*)&t1h;
            av[2] = *(uint32_t*)&t2h;
            av[3] = *(uint32_t*)&t3h;
            mma16816(lacc, av, ONES_H2, ONES_H2);
#pragma unroll
            for (int db = 0; db < 8; db++) {
                uint32_t vr[4];
                ldsm_x4_t(vr, vb + swoff(kp * 16 + ((grp & 1) << 3) + lr, db * 2 + (grp >> 1)));
                mma16816(oa[db * 2], av, vr[0], vr[1]);
                mma16816(oa[db * 2 + 1], av, vr[2], vr[3]);
            }
        }

        __syncthreads();
        if (kt + 2 < nkt) load_kv(kt + 2, s);
    }

    __syncthreads();
    {
        float inv0 = 1.f / lacc[0], inv1 = 1.f / lacc[2];
        __half* ost = (__half*)smem_raw;
        int r0 = (wid << 4) + (lid >> 2);
#pragma unroll
        for (int ot = 0; ot < 16; ot++) {
            int col = ot * 8 + ((lid & 3) << 1);
            *(__half2*)(ost + r0 * OROWH + col) =
                __floats2half2_rn(oa[ot][0] * inv0, oa[ot][1] * inv0);
            *(__half2*)(ost + (r0 + 8) * OROWH + col) =
                __floats2half2_rn(oa[ot][2] * inv1, oa[ot][3] * inv1);
        }
    }
    __syncthreads();
    {
        int row = tid >> 1;
        int hf = tid & 1;
        const __half* src = (const __half*)smem_raw + row * OROWH + hf * 64;
        __half* dst = out + ((size_t)(b * T_SEQ + q0 + row)) * CDIM + h * HD + hf * 64;
#pragma unroll
        for (int j = 0; j < 8; j++)
            ((uint4*)dst)[j] = ((const uint4*)src)[j];
    }
}

// ---------------- launch ----------------------------------------------------
extern "C" void kernel_launch(void* const* d_in, const int* in_sizes, int n_in,
                              void* d_out, int out_size) {
    const float* x      = (const float*)d_in[0];
    const float* W_attn = (const float*)d_in[1];
    const float* W_proj = (const float*)d_in[2];
    const float* w_std  = (const float*)d_in[3];
    const float* w_rec  = (const float*)d_in[4];
    float* out = (float*)d_out;

    __half *xh, *Wah, *Wph, *atth, *Qh, *Kh, *Vh;
    cudaGetSymbolAddress((void**)&xh, g_xh);
    cudaGetSymbolAddress((void**)&Wah, g_Wah);
    cudaGetSymbolAddress((void**)&Wph, g_Wph);
    cudaGetSymbolAddress((void**)&atth, g_atth);
    cudaGetSymbolAddress((void**)&Qh, g_Qh);
    cudaGetSymbolAddress((void**)&Kh, g_Kh);
    cudaGetSymbolAddress((void**)&Vh, g_Vh);

    const int M = BATCH * T_SEQ;  // 4096

    cudaFuncSetAttribute(hgemm_mma<0>, cudaFuncAttributeMaxDynamicSharedMemorySize, GSMEM);
    cudaFuncSetAttribute(hgemm_mma<1>, cudaFuncAttributeMaxDynamicSharedMemorySize, GSMEM);
    cudaFuncSetAttribute(attn_mma, cudaFuncAttributeMaxDynamicSharedMemorySize, ASMEM);

    {
        int na4 = (M * CDIM) / 4;
        int nb4 = (FDIM * CDIM) / 4;
        int nc4 = (CDIM * CDIM) / 4;
        int tot = na4 + nb4 + nc4;
        f2h3<<<(tot + 255) / 256, 256>>>(x, xh, na4, W_attn, Wah, nb4,
                                         W_proj, Wph, nc4);
    }
    {
        dim3 grid(FDIM / 128, M / 128);
        hgemm_mma<1><<<grid, 256, GSMEM>>>(xh, Wah, nullptr, w_std, w_rec,
                                           Qh, Kh, Vh, M, FDIM);
    }
    {
        dim3 grid((T_SEQ / 64) * BATCH * HEADS);  // 1024, globally heavy-first
        attn_mma<<<grid, 128, ASMEM>>>(Qh, Kh, Vh, atth);
    }
    {
        dim3 grid(CDIM / 128, M / 128);
        hgemm_mma<0><<<grid, 256, GSMEM>>>(atth, Wph, out, nullptr, nullptr,
                                           nullptr, nullptr, nullptr, M, CDIM);
    }
}

// round 16
// speedup vs baseline: 1.0402x; 1.0402x over previous
#include <cuda_runtime.h>
#include <cuda_fp16.h>
#include <math.h>
#include <stdint.h>

#define T_SEQ 2048
#define BATCH 2
#define CDIM  2048
#define HEADS 16
#define HD    128
#define DSTD  120
#define RLOW  8
#define FDIM  6144

// ---------------- scratch (device globals; no allocations) ----------------
__device__ __align__(16) __half g_xh[(size_t)BATCH * T_SEQ * CDIM];
__device__ __align__(16) __half g_Wah[(size_t)FDIM * CDIM];
__device__ __align__(16) __half g_Wph[(size_t)CDIM * CDIM];
__device__ __align__(16) __half g_atth[(size_t)BATCH * T_SEQ * CDIM];
__device__ __align__(16) __half g_Qh[(size_t)BATCH * HEADS * T_SEQ * HD];
__device__ __align__(16) __half g_Kh[(size_t)BATCH * HEADS * T_SEQ * HD];
__device__ __align__(16) __half g_Vh[(size_t)BATCH * HEADS * T_SEQ * HD];

// ---------------- PTX helpers ----------------------------------------------
__device__ __forceinline__ uint32_t smem_u32(const void* p) {
    uint32_t a;
    asm("{ .reg .u64 t; cvta.to.shared.u64 t, %1; cvt.u32.u64 %0, t; }"
        : "=r"(a) : "l"(p));
    return a;
}
__device__ __forceinline__ void cp16(uint32_t saddr, const void* gaddr) {
    asm volatile("cp.async.cg.shared.global [%0], [%1], 16;"
                 :: "r"(saddr), "l"(gaddr) : "memory");
}
__device__ __forceinline__ void ldsm_x4(uint32_t* r, uint32_t addr) {
    asm volatile("ldmatrix.sync.aligned.m8n8.x4.shared.b16 {%0,%1,%2,%3}, [%4];"
                 : "=r"(r[0]), "=r"(r[1]), "=r"(r[2]), "=r"(r[3]) : "r"(addr));
}
__device__ __forceinline__ void ldsm_x4_t(uint32_t* r, uint32_t addr) {
    asm volatile("ldmatrix.sync.aligned.m8n8.x4.trans.shared.b16 {%0,%1,%2,%3}, [%4];"
                 : "=r"(r[0]), "=r"(r[1]), "=r"(r[2]), "=r"(r[3]) : "r"(addr));
}
__device__ __forceinline__ void mma16816(float* c, const uint32_t* a,
                                         uint32_t b0, uint32_t b1) {
    asm volatile(
        "mma.sync.aligned.m16n8k16.row.col.f32.f16.f16.f32 "
        "{%0,%1,%2,%3},{%4,%5,%6,%7},{%8,%9},{%0,%1,%2,%3};"
        : "+f"(c[0]), "+f"(c[1]), "+f"(c[2]), "+f"(c[3])
        : "r"(a[0]), "r"(a[1]), "r"(a[2]), "r"(a[3]), "r"(b0), "r"(b1));
}

// ---------------- HMMA GEMM: C[M,N]=A[M,K]*B[N,K]^T, compile-time KT --------
// block 128x128, warp 64x32 (8 warps), BK=64, 3-stage cp.async, KT=K/64=32.
#define GSMEM (3 * 32768)
#define KT_C  32   // both GEMMs have K = 2048

template <int EPI>
__global__ void __launch_bounds__(256, 2)
hgemm_mma(const __half* __restrict__ A, const __half* __restrict__ B,
          float* __restrict__ C,
          const float* __restrict__ w_std, const float* __restrict__ w_rec,
          __half* __restrict__ Qd, __half* __restrict__ Kd,
          __half* __restrict__ Vd, int M, int N) {
    constexpr int K = KT_C * 64;
    extern __shared__ __align__(1024) char smem_raw[];
    const uint32_t smem = smem_u32(smem_raw);
    const int tid = threadIdx.x;
    const int wid = tid >> 5;
    const int lid = tid & 31;
    const int m0 = blockIdx.y << 7;
    const int n0 = blockIdx.x << 7;
    const int wm0 = (wid & 1) << 6;
    const int wn0 = (wid >> 1) << 5;

    const int r = tid >> 1;
    const int hs = tid & 1;
    const __half* Ag = A + (size_t)(m0 + r) * K + hs * 32;
    const __half* Bg = B + (size_t)(n0 + r) * K + hs * 32;
    const uint32_t swb = r * 128 + hs * 64;

    auto load_stage = [&](int kt, int s) {
        uint32_t ab = smem + s * 32768;
        uint32_t bb = ab + 16384;
        const __half* ag = Ag + kt * 64;
        const __half* bg = Bg + kt * 64;
#pragma unroll
        for (int j = 0; j < 4; j++) {
            uint32_t off = swb + j * 16;
            uint32_t sw = off ^ ((off >> 3) & 0x70);
            cp16(ab + sw, ag + j * 8);
            cp16(bb + sw, bg + j * 8);
        }
        asm volatile("cp.async.commit_group;" ::: "memory");
    };

    float acc[4][4][4];
#pragma unroll
    for (int mt = 0; mt < 4; mt++)
#pragma unroll
        for (int nt = 0; nt < 4; nt++)
#pragma unroll
            for (int e = 0; e < 4; e++) acc[mt][nt][e] = 0.f;

    load_stage(0, 0);
    load_stage(1, 1);

    const int grp = lid >> 3;
    const int lr = lid & 7;
    const int arow = wm0 + ((grp & 1) << 3) + lr;
    const int acol = (grp >> 1) << 3;
    const int brow = wn0 + ((grp & 1) << 3) + lr;

    auto compute_tile = [&](int s) {
        const uint32_t ab = smem + s * 32768;
        const uint32_t bb = ab + 16384;
#pragma unroll
        for (int ks = 0; ks < 4; ks++) {
            uint32_t a_regs[4][4];
#pragma unroll
            for (int mt = 0; mt < 4; mt++) {
                uint32_t off = (uint32_t)(arow + mt * 16) * 128 + (acol + ks * 16) * 2;
                ldsm_x4(a_regs[mt], ab + (off ^ ((off >> 3) & 0x70)));
            }
            uint32_t b_regs[2][4];
#pragma unroll
            for (int np = 0; np < 2; np++) {
                uint32_t off = (uint32_t)(brow + np * 16) * 128 + (acol + ks * 16) * 2;
                ldsm_x4(b_regs[np], bb + (off ^ ((off >> 3) & 0x70)));
            }
#pragma unroll
            for (int mt = 0; mt < 4; mt++)
#pragma unroll
                for (int nt = 0; nt < 4; nt++) {
                    uint32_t b0 = b_regs[nt >> 1][nt & 1];
                    uint32_t b1 = b_regs[nt >> 1][(nt & 1) + 2];
                    mma16816(acc[mt][nt], a_regs[mt], b0, b1);
                }
        }
    };

    // body: KT-2 = 30 iterations, unroll 6 (measured optimum)
#pragma unroll 6
    for (int kt = 0; kt < KT_C - 2; kt++) {
        asm volatile("cp.async.wait_group 1;" ::: "memory");
        __syncthreads();
        load_stage(kt + 2, (kt + 2) % 3);
        compute_tile(kt % 3);
    }
    asm volatile("cp.async.wait_group 1;" ::: "memory");
    __syncthreads();
    compute_tile((KT_C - 2) % 3);
    asm volatile("cp.async.wait_group 0;" ::: "memory");
    __syncthreads();
    compute_tile((KT_C - 1) % 3);

    const int row0 = m0 + wm0 + (lid >> 2);
    const int col0 = n0 + wn0 + (lid & 3) * 2;

    if (EPI == 0) {
#pragma unroll
        for (int mt = 0; mt < 4; mt++)
#pragma unroll
            for (int nt = 0; nt < 4; nt++) {
                float* p0 = C + (size_t)(row0 + mt * 16) * N + col0 + nt * 8;
                float* p1 = C + (size_t)(row0 + mt * 16 + 8) * N + col0 + nt * 8;
                *(float2*)p0 = make_float2(acc[mt][nt][0], acc[mt][nt][1]);
                *(float2*)p1 = make_float2(acc[mt][nt][2], acc[mt][nt][3]);
            }
    } else {
        const float ascale = 0.08838834764831845f;  // 1/sqrt(128)
        const int b = m0 >> 11;
#pragma unroll
        for (int nt = 0; nt < 4; nt++) {
            int f = col0 + nt * 8;
            __half* dst;
            int h, d;
            float scl;
            if (f < 1920) {
                h = f / 120; d = f - h * 120;
                scl = sqrtf(fmaxf(w_std[h], 1e-8f)) * ascale;
                dst = Qd;
            } else if (f < 3840) {
                int g = f - 1920; h = g / 120; d = g - h * 120;
                scl = sqrtf(fmaxf(w_std[h], 1e-8f));
                dst = Kd;
            } else if (f < 5888) {
                int g = f - 3840; h = g >> 7; d = g & 127;
                scl = 1.f;
                dst = Vd;
            } else if (f < 6016) {
                int g = f - 5888; h = g >> 3; d = 120 + (g & 7);
                float wrv = w_rec[h];
                if (wrv > 0.1f) { scl = sqrtf(fmaxf(wrv, 1e-8f)); dst = Kd; }
                else { scl = sqrtf(fmaxf(w_std[h], 1e-8f)) * ascale; dst = Qd; }
            } else {
                int g = f - 6016; h = g >> 3; d = 120 + (g & 7);
                float wrv = w_rec[h];
                if (wrv > 0.1f) { scl = sqrtf(fmaxf(wrv, 1e-8f)) * ascale; dst = Qd; }
                else { scl = sqrtf(fmaxf(w_std[h], 1e-8f)); dst = Kd; }
            }
            __half* base = dst + (((size_t)(b * HEADS + h)) << 18) + d;
#pragma unroll
            for (int mt = 0; mt < 4; mt++) {
                int t0 = (row0 + mt * 16) & (T_SEQ - 1);
                *(__half2*)(base + ((size_t)t0 << 7)) =
                    __floats2half2_rn(acc[mt][nt][0] * scl, acc[mt][nt][1] * scl);
                *(__half2*)(base + ((size_t)(t0 + 8) << 7)) =
                    __floats2half2_rn(acc[mt][nt][2] * scl, acc[mt][nt][3] * scl);
            }
        }
    }
}

// ---------------- fused fp32 -> fp16 conversion (3 arrays, 1 launch) -------
__global__ void f2h3(const float* __restrict__ a, __half* __restrict__ oa_, int na4,
                     const float* __restrict__ b, __half* __restrict__ ob_, int nb4,
                     const float* __restrict__ c, __half* __restrict__ oc_, int nc4) {
    int i = blockIdx.x * blockDim.x + threadIdx.x;
    const float* src;
    __half* dst;
    if (i < na4) { src = a; dst = oa_; }
    else if (i < na4 + nb4) { i -= na4; src = b; dst = ob_; }
    else { i -= na4 + nb4; if (i >= nc4) return; src = c; dst = oc_; }
    float4 v = ((const float4*)src)[i];
    ((__half2*)dst)[2 * i] = __floats2half2_rn(v.x, v.y);
    ((__half2*)dst)[2 * i + 1] = __floats2half2_rn(v.z, v.w);
}

// ---------------- HMMA causal flash attention ------------------------------
// 64-query tile, Q in regs, 2-stage KV cp.async, tensor-core row sums,
// heavy-first 1D grid, overlapped Q/KV startup, coalesced smem-staged O.
#define ASMEM 65536
#define OROWH 136
#define ONES_H2 0x3C003C00u  // half2(1.0, 1.0)
__device__ __forceinline__ uint32_t swoff(int row, int c16) {
    return (uint32_t)row * 256 + (uint32_t)((c16 ^ (row & 7)) * 16);
}

__global__ void __launch_bounds__(128, 3)
attn_mma(const __half* __restrict__ Qh, const __half* __restrict__ Kh,
         const __half* __restrict__ Vh, __half* __restrict__ out) {
    extern __shared__ __align__(1024) char smem_raw[];
    const uint32_t sb = smem_u32(smem_raw);
    const int tid = threadIdx.x;
    const int wid = tid >> 5;
    const int lid = tid & 31;
    const int grp = lid >> 3;
    const int lr = lid & 7;
    const int bh = blockIdx.x & 31;
    const int qi = (T_SEQ / 64 - 1) - (blockIdx.x >> 5);  // globally heavy-first
    const int b = bh >> 4;
    const int h = bh & 15;
    const int q0 = qi << 6;
    const int nkt = qi + 1;

    // Q staged in stage-1 K region [32K,48K); KV(1) deferred until Q consumed.
    const __half* Qg = Qh + ((size_t)bh * T_SEQ + q0) * HD;
    {
        uint32_t qb = sb + 32768;
#pragma unroll
        for (int i = 0; i < 8; i++) {
            int idx = tid + i * 128;
            int row = idx >> 4;
            int c = idx & 15;
            cp16(qb + swoff(row, c), Qg + (size_t)row * HD + c * 8);
        }
        asm volatile("cp.async.commit_group;" ::: "memory");
    }

    auto load_kv = [&](int kt, int s) {
        const __half* Kg = Kh + ((size_t)bh * T_SEQ + kt * 64) * HD;
        const __half* Vg = Vh + ((size_t)bh * T_SEQ + kt * 64) * HD;
        uint32_t kb = sb + (uint32_t)s * 32768;
        uint32_t vb = kb + 16384;
#pragma unroll
        for (int i = 0; i < 8; i++) {
            int idx = tid + i * 128;
            int row = idx >> 4;
            int c = idx & 15;
            uint32_t o = swoff(row, c);
            cp16(kb + o, Kg + (size_t)row * HD + c * 8);
            cp16(vb + o, Vg + (size_t)row * HD + c * 8);
        }
        asm volatile("cp.async.commit_group;" ::: "memory");
    };

    load_kv(0, 0);
    asm volatile("cp.async.wait_group 1;" ::: "memory");
    __syncthreads();

    uint32_t qf[8][4];
    {
        uint32_t qb = sb + 32768;
        int arow = (wid << 4) + ((grp & 1) << 3) + lr;
        int ach = (grp >> 1);
#pragma unroll
        for (int ks = 0; ks < 8; ks++)
            ldsm_x4(qf[ks], qb + swoff(arow, ks * 2 + ach));
    }
    __syncthreads();
    if (nkt > 1) load_kv(1, 1);

    float oa[16][4];
#pragma unroll
    for (int ot = 0; ot < 16; ot++)
#pragma unroll
        for (int e = 0; e < 4; e++) oa[ot][e] = 0.f;
    float lacc[4] = {0.f, 0.f, 0.f, 0.f};
    float m0 = -1e30f, m1 = -1e30f;

    for (int kt = 0; kt < nkt; kt++) {
        const int s = kt & 1;
        if (kt + 1 < nkt)
            asm volatile("cp.async.wait_group 1;" ::: "memory");
        else
            asm volatile("cp.async.wait_group 0;" ::: "memory");
        __syncthreads();

        const uint32_t kb = sb + (uint32_t)s * 32768;
        const uint32_t vb = kb + 16384;

        float sa[8][4];
#pragma unroll
        for (int nt = 0; nt < 8; nt++)
#pragma unroll
            for (int e = 0; e < 4; e++) sa[nt][e] = 0.f;

        const int brb = ((grp & 1) << 3) + lr;
        const int bch = (grp >> 1);
#pragma unroll
        for (int ks = 0; ks < 8; ks++) {
            uint32_t br[4][4];
#pragma unroll
            for (int np = 0; np < 4; np++)
                ldsm_x4(br[np], kb + swoff(np * 16 + brb, ks * 2 + bch));
#pragma unroll
            for (int nt = 0; nt < 8; nt++)
                mma16816(sa[nt], qf[ks], br[nt >> 1][nt & 1], br[nt >> 1][(nt & 1) + 2]);
        }

        if (kt == qi) {
            int qr = (wid << 4) + (lid >> 2);
#pragma unroll
            for (int nt = 0; nt < 8; nt++) {
                int cb = nt * 8 + ((lid & 3) << 1);
#pragma unroll
                for (int e = 0; e < 4; e++) {
                    int col = cb + (e & 1);
                    int row = qr + ((e >> 1) << 3);
                    if (col > row) sa[nt][e] = -1e30f;
                }
            }
        }

        float mx0 = -1e30f, mx1 = -1e30f;
#pragma unroll
        for (int nt = 0; nt < 8; nt++) {
            mx0 = fmaxf(mx0, fmaxf(sa[nt][0], sa[nt][1]));
            mx1 = fmaxf(mx1, fmaxf(sa[nt][2], sa[nt][3]));
        }
        mx0 = fmaxf(mx0, __shfl_xor_sync(0xffffffffu, mx0, 1));
        mx0 = fmaxf(mx0, __shfl_xor_sync(0xffffffffu, mx0, 2));
        mx1 = fmaxf(mx1, __shfl_xor_sync(0xffffffffu, mx1, 1));
        mx1 = fmaxf(mx1, __shfl_xor_sync(0xffffffffu, mx1, 2));

        float mn0 = fmaxf(m0, mx0), mn1 = fmaxf(m1, mx1);
        float al0 = __expf(m0 - mn0), al1 = __expf(m1 - mn1);
        m0 = mn0; m1 = mn1;

#pragma unroll
        for (int nt = 0; nt < 8; nt++) {
            sa[nt][0] = __expf(sa[nt][0] - mn0);
            sa[nt][1] = __expf(sa[nt][1] - mn0);
            sa[nt][2] = __expf(sa[nt][2] - mn1);
            sa[nt][3] = __expf(sa[nt][3] - mn1);
        }

#pragma unroll
        for (int ot = 0; ot < 16; ot++) {
            oa[ot][0] *= al0; oa[ot][1] *= al0;
            oa[ot][2] *= al1; oa[ot][3] *= al1;
        }
        lacc[0] *= al0;
        lacc[2] *= al1;

#pragma unroll
        for (int kp = 0; kp < 4; kp++) {
            uint32_t av[4];
            __half2 t0h = __floats2half2_rn(sa[2 * kp][0], sa[2 * kp][1]);
            __half2 t1h = __floats2half2_rn(sa[2 * kp][2], sa[2 * kp][3]);
            __half2 t2h = __floats2half2_rn(sa[2 * kp + 1][0], sa[2 * kp + 1][1]);
            __half2 t3h = __floats2half2_rn(sa[2 * kp + 1][2], sa[2 * kp + 1][3]);
            av[0] = *(uint32_t*)&t0h;
            av[1] = *(uint32_t*)&t1h;
            av[2] = *(uint32_t*)&t2h;
            av[3] = *(uint32_t*)&t3h;
            mma16816(lacc, av, ONES_H2, ONES_H2);
#pragma unroll
            for (int db = 0; db < 8; db++) {
                uint32_t vr[4];
                ldsm_x4_t(vr, vb + swoff(kp * 16 + ((grp & 1) << 3) + lr, db * 2 + (grp >> 1)));
                mma16816(oa[db * 2], av, vr[0], vr[1]);
                mma16816(oa[db * 2 + 1], av, vr[2], vr[3]);
            }
        }

        __syncthreads();
        if (kt + 2 < nkt) load_kv(kt + 2, s);
    }

    __syncthreads();
    {
        float inv0 = 1.f / lacc[0], inv1 = 1.f / lacc[2];
        __half* ost = (__half*)smem_raw;
        int r0 = (wid << 4) + (lid >> 2);
#pragma unroll
        for (int ot = 0; ot < 16; ot++) {
            int col = ot * 8 + ((lid & 3) << 1);
            *(__half2*)(ost + r0 * OROWH + col) =
                __floats2half2_rn(oa[ot][0] * inv0, oa[ot][1] * inv0);
            *(__half2*)(ost + (r0 + 8) * OROWH + col) =
                __floats2half2_rn(oa[ot][2] * inv1, oa[ot][3] * inv1);
        }
    }
    __syncthreads();
    {
        int row = tid >> 1;
        int hf = tid & 1;
        const __half* src = (const __half*)smem_raw + row * OROWH + hf * 64;
        __half* dst = out + ((size_t)(b * T_SEQ + q0 + row)) * CDIM + h * HD + hf * 64;
#pragma unroll
        for (int j = 0; j < 8; j++)
            ((uint4*)dst)[j] = ((const uint4*)src)[j];
    }
}

// ---------------- launch ----------------------------------------------------
extern "C" void kernel_launch(void* const* d_in, const int* in_sizes, int n_in,
                              void* d_out, int out_size) {
    const float* x      = (const float*)d_in[0];
    const float* W_attn = (const float*)d_in[1];
    const float* W_proj = (const float*)d_in[2];
    const float* w_std  = (const float*)d_in[3];
    const float* w_rec  = (const float*)d_in[4];
    float* out = (float*)d_out;

    __half *xh, *Wah, *Wph, *atth, *Qh, *Kh, *Vh;
    cudaGetSymbolAddress((void**)&xh, g_xh);
    cudaGetSymbolAddress((void**)&Wah, g_Wah);
    cudaGetSymbolAddress((void**)&Wph, g_Wph);
    cudaGetSymbolAddress((void**)&atth, g_atth);
    cudaGetSymbolAddress((void**)&Qh, g_Qh);
    cudaGetSymbolAddress((void**)&Kh, g_Kh);
    cudaGetSymbolAddress((void**)&Vh, g_Vh);

    const int M = BATCH * T_SEQ;  // 4096

    cudaFuncSetAttribute(hgemm_mma<0>, cudaFuncAttributeMaxDynamicSharedMemorySize, GSMEM);
    cudaFuncSetAttribute(hgemm_mma<1>, cudaFuncAttributeMaxDynamicSharedMemorySize, GSMEM);
    cudaFuncSetAttribute(attn_mma, cudaFuncAttributeMaxDynamicSharedMemorySize, ASMEM);

    {
        int na4 = (M * CDIM) / 4;
        int nb4 = (FDIM * CDIM) / 4;
        int nc4 = (CDIM * CDIM) / 4;
        int tot = na4 + nb4 + nc4;
        f2h3<<<(tot + 255) / 256, 256>>>(x, xh, na4, W_attn, Wah, nb4,
                                         W_proj, Wph, nc4);
    }
    {
        dim3 grid(FDIM / 128, M / 128);
        hgemm_mma<1><<<grid, 256, GSMEM>>>(xh, Wah, nullptr, w_std, w_rec,
                                           Qh, Kh, Vh, M, FDIM);
    }
    {
        dim3 grid((T_SEQ / 64) * BATCH * HEADS);  // 1024, globally heavy-first
        attn_mma<<<grid, 128, ASMEM>>>(Qh, Kh, Vh, atth);
    }
    {
        dim3 grid(CDIM / 128, M / 128);
        hgemm_mma<0><<<grid, 256, GSMEM>>>(atth, Wph, out, nullptr, nullptr,
                                           nullptr, nullptr, nullptr, M, CDIM);
    }
}